// round 16
// baseline (speedup 1.0000x reference)
#include <cuda_runtime.h>
#include <math.h>
#include <stdint.h>

#define Bb 8
#define Tt 1024
#define Dd 512
#define Hh 8
#define DHh 64
#define DEPTHL 8
#define FFf 2048
#define NHh 8
#define BSz 64
#define NBk 16
#define NC (NHh*NBk)
#define BHn (Bb*Hh)
#define SEG (NHh*Tt)

#define PIT 36   // attention packed-pair row pitch (words)

// ---------------- scratch ----------------
__device__ float g_x1[Bb*Tt*Dd];
__device__ float g_x2[Bb*Tt*Dd];
__device__ float g_qk[Bb*Tt*Dd];
__device__ float g_v [Bb*Tt*Dd];
__device__ float g_bo[(size_t)BHn*NHh*Tt*DHh];
__device__ float g_slog[BHn*NHh*Tt];
__device__ int   g_st [BHn*SEG];
__device__ int   g_bkt[BHn*SEG];
__device__ float g_pool[Bb*Dd];
// packed bf16 hi/lo activations (pair along feature dim)
__device__ unsigned g_xnh[Bb*Tt*Dd/2],  g_xnl[Bb*Tt*Dd/2];
__device__ unsigned g_ffhh[Bb*Tt*FFf/2], g_ffhl[Bb*Tt*FFf/2];
__device__ unsigned g_aoh[Bb*Tt*Dd/2],  g_aol[Bb*Tt*Dd/2];
// packed bf16 hi/lo weights (pair along K dim): [K/2][N] words per layer
__device__ unsigned g_WqkH[DEPTHL*256*512], g_WqkL[DEPTHL*256*512];
__device__ unsigned g_WvH [DEPTHL*256*512], g_WvL [DEPTHL*256*512];
__device__ unsigned g_WoH [DEPTHL*256*512], g_WoL [DEPTHL*256*512];
__device__ unsigned g_W1H [DEPTHL*256*2048], g_W1L [DEPTHL*256*2048];
__device__ unsigned g_W2H [DEPTHL*1024*512], g_W2L [DEPTHL*1024*512];

// ---------------- helpers ----------------
__device__ __forceinline__ float gelu_fast(float x) {
    float u = 0.7978845608028654f*(x + 0.044715f*x*x*x);
    float t = 1.f - 2.f/(__expf(2.f*u) + 1.f);
    return 0.5f*x*(1.f + t);
}

__device__ __forceinline__ float blockReduceSum256(float val, float* red) {
    #pragma unroll
    for (int o = 16; o; o >>= 1) val += __shfl_xor_sync(0xffffffffu, val, o);
    int w = threadIdx.x >> 5;
    if ((threadIdx.x & 31) == 0) red[w] = val;
    __syncthreads();
    float r = (threadIdx.x < 8) ? red[threadIdx.x] : 0.f;
    if (threadIdx.x < 32) {
        #pragma unroll
        for (int o = 4; o; o >>= 1) r += __shfl_xor_sync(0xffffffffu, r, o);
        if (threadIdx.x == 0) red[0] = r;
    }
    __syncthreads();
    float out = red[0];
    __syncthreads();
    return out;
}

__device__ __forceinline__ void mma_bf16(float* c,
    unsigned a0, unsigned a1, unsigned a2, unsigned a3,
    unsigned b0, unsigned b1) {
    asm volatile(
        "mma.sync.aligned.m16n8k16.row.col.f32.bf16.bf16.f32 "
        "{%0,%1,%2,%3}, {%4,%5,%6,%7}, {%8,%9}, {%0,%1,%2,%3};"
        : "+f"(c[0]), "+f"(c[1]), "+f"(c[2]), "+f"(c[3])
        : "r"(a0), "r"(a1), "r"(a2), "r"(a3), "r"(b0), "r"(b1));
}

// split (x0,x1) into packed bf16x2 hi and lo (residual); x0 in low half.
__device__ __forceinline__ void split_pair(float x0, float x1,
                                           unsigned &hi, unsigned &lo) {
    unsigned h;
    asm("cvt.rn.bf16x2.f32 %0, %1, %2;" : "=r"(h) : "f"(x1), "f"(x0));
    float h0 = __uint_as_float(h << 16);
    float h1 = __uint_as_float(h & 0xffff0000u);
    float l0 = x0 - h0, l1 = x1 - h1;
    asm("cvt.rn.bf16x2.f32 %0, %1, %2;" : "=r"(lo) : "f"(l1), "f"(l0));
    hi = h;
}

__device__ __forceinline__ void cp16(void* smem, const void* gmem) {
    unsigned s = (unsigned)__cvta_generic_to_shared(smem);
    asm volatile("cp.async.ca.shared.global [%0], [%1], 16;" :: "r"(s), "l"(gmem));
}

// ---------------- weight pre-split: [2*rows2][N] fp32 -> [rows2][N] hi/lo words ----------------
__global__ void convw_kernel(const float* __restrict__ W,
                             unsigned* __restrict__ Wh, unsigned* __restrict__ Wl,
                             int rows2, int N) {
    int idx = blockIdx.x*256 + threadIdx.x;
    if (idx >= rows2*N) return;
    int r2 = idx / N, n = idx - r2*N;
    float x0 = W[(size_t)(2*r2)*N + n];
    float x1 = W[(size_t)(2*r2+1)*N + n];
    unsigned h, l;
    split_pair(x0, x1, h, l);
    Wh[idx] = h; Wl[idx] = l;
}

// ---------------- embedding ----------------
__global__ void embed_kernel(const int* __restrict__ ids,
                             const float* __restrict__ tok,
                             const float* __restrict__ pos,
                             float* __restrict__ x1, float* __restrict__ x2) {
    int i = blockIdx.x*256 + threadIdx.x;
    if (i >= Bb*Tt*Dd) return;
    int d = i & (Dd-1);
    int bt = i >> 9;
    int t = bt & (Tt-1);
    int id = ids[bt];
    if (id < 0) id = 0;
    if (id >= 6400) id = 6399;
    float v = tok[(size_t)id*Dd + d] + pos[t*Dd + d];
    x1[i] = v; x2[i] = v;
}

// ---------------- layernorm: emits packed hi/lo pairs ----------------
__global__ void ln_kernel(const float* __restrict__ x, const float* __restrict__ xb,
                          unsigned* __restrict__ yh, unsigned* __restrict__ yl,
                          const float* __restrict__ g, const float* __restrict__ bia) {
    __shared__ float red[8];
    int row = blockIdx.x;
    int i = threadIdx.x;                     // pair index 0..255
    float2 xv = *(const float2*)&x[(size_t)row*Dd + 2*i];
    float v0 = xv.x, v1 = xv.y;
    if (xb) {
        float2 bv = *(const float2*)&xb[(size_t)row*Dd + 2*i];
        v0 = 0.5f*(v0 + bv.x); v1 = 0.5f*(v1 + bv.y);
    }
    float s = blockReduceSum256(v0+v1, red);
    float mean = s * (1.f/512.f);
    float d0 = v0 - mean, d1 = v1 - mean;
    float s2 = blockReduceSum256(d0*d0 + d1*d1, red);
    float inv = rsqrtf(s2*(1.f/512.f) + 1e-5f);
    float2 gv = *(const float2*)&g[2*i];
    float2 bb = *(const float2*)&bia[2*i];
    float y0 = d0*inv*gv.x + bb.x;
    float y1 = d1*inv*gv.y + bb.y;
    unsigned h, l;
    split_pair(y0, y1, h, l);
    yh[(size_t)row*256 + i] = h;
    yl[(size_t)row*256 + i] = l;
}

// ---------------- tensor-core GEMM: pre-split bf16 operands, pure LDS+MMA mainloop ----------------
// A: packed [M][K/2] hi/lo; B: packed [K/2][N] hi/lo.
// EPI: 0 = store fp32, 1 = gelu(acc+bias) -> split store, 3 = Cf += acc, 4 = Cf += acc + bias
template<int EPI>
__global__ void __launch_bounds__(256) gemm_kernel(
        const unsigned* __restrict__ Ah, const unsigned* __restrict__ Al,
        const unsigned* __restrict__ Bh0, const unsigned* __restrict__ Bl0,
        const float* __restrict__ bias,
        float* __restrict__ Cf, unsigned* __restrict__ Ch, unsigned* __restrict__ Cl,
        int M, int K,
        const unsigned* __restrict__ B2h, const unsigned* __restrict__ B2l,
        float* __restrict__ C2f,
        int nHalf, int Nplain) {
    __shared__ unsigned AsH[2][128][12], AsL[2][128][12];
    __shared__ unsigned BsH[2][8][132],  BsL[2][8][132];

    const int tid  = threadIdx.x;
    const int lane = tid & 31;
    const int warp = tid >> 5;
    const int wm = warp & 1;
    const int wn = warp >> 1;
    const int gid = lane >> 2;
    const int qid = lane & 3;
    const int bm = blockIdx.y*128;

    const unsigned* Buh = Bh0;
    const unsigned* Bul = Bl0;
    float* Cu = Cf;
    int bn = blockIdx.x*128;
    int Nld = Nplain;
    if (B2h != nullptr) {
        Nld = nHalf;
        if (bn >= nHalf) { Buh = B2h; Bul = B2l; Cu = C2f; bn -= nHalf; }
    }
    const int K2 = K >> 1;

    float c[4][4][4];
    #pragma unroll
    for (int mt = 0; mt < 4; mt++)
        #pragma unroll
        for (int nt = 0; nt < 4; nt++)
            #pragma unroll
            for (int e = 0; e < 4; e++) c[mt][nt][e] = 0.f;

    const int ar = tid >> 1, aw = (tid & 1)*4;   // A: row 0..127, word 0 or 4
    const int br = tid >> 5, bc = (tid & 31)*4;  // B: k-pair row 0..7, col-word

    const int nk = K >> 4;

    {
        cp16(&AsH[0][ar][aw], Ah + (size_t)(bm + ar)*K2 + aw);
        cp16(&AsL[0][ar][aw], Al + (size_t)(bm + ar)*K2 + aw);
        cp16(&BsH[0][br][bc], Buh + (size_t)br*Nld + bn + bc);
        cp16(&BsL[0][br][bc], Bul + (size_t)br*Nld + bn + bc);
        asm volatile("cp.async.commit_group;");
        asm volatile("cp.async.wait_group 0;");
    }
    __syncthreads();

    for (int kt = 0; kt < nk; kt++) {
        const int cur = kt & 1;
        if (kt + 1 < nk) {
            const int nxt = cur ^ 1;
            int k8 = (kt + 1)*8;               // pair-word offset
            cp16(&AsH[nxt][ar][aw], Ah + (size_t)(bm + ar)*K2 + k8 + aw);
            cp16(&AsL[nxt][ar][aw], Al + (size_t)(bm + ar)*K2 + k8 + aw);
            cp16(&BsH[nxt][br][bc], Buh + (size_t)(k8 + br)*Nld + bn + bc);
            cp16(&BsL[nxt][br][bc], Bul + (size_t)(k8 + br)*Nld + bn + bc);
            asm volatile("cp.async.commit_group;");
        }

        unsigned ah[4][4], alr[4][4];
        #pragma unroll
        for (int mt = 0; mt < 4; mt++) {
            int r0 = wm*64 + mt*16 + gid;
            ah[mt][0] = AsH[cur][r0  ][qid];   alr[mt][0] = AsL[cur][r0  ][qid];
            ah[mt][1] = AsH[cur][r0+8][qid];   alr[mt][1] = AsL[cur][r0+8][qid];
            ah[mt][2] = AsH[cur][r0  ][qid+4]; alr[mt][2] = AsL[cur][r0  ][qid+4];
            ah[mt][3] = AsH[cur][r0+8][qid+4]; alr[mt][3] = AsL[cur][r0+8][qid+4];
        }
        #pragma unroll
        for (int nt = 0; nt < 4; nt++) {
            int nc = wn*32 + nt*8 + gid;
            unsigned b0h = BsH[cur][qid  ][nc], b0l = BsL[cur][qid  ][nc];
            unsigned b1h = BsH[cur][qid+4][nc], b1l = BsL[cur][qid+4][nc];
            #pragma unroll
            for (int mt = 0; mt < 4; mt++) {
                mma_bf16(c[mt][nt], ah[mt][0],ah[mt][1],ah[mt][2],ah[mt][3], b0h, b1h);
                mma_bf16(c[mt][nt], ah[mt][0],ah[mt][1],ah[mt][2],ah[mt][3], b0l, b1l);
                mma_bf16(c[mt][nt], alr[mt][0],alr[mt][1],alr[mt][2],alr[mt][3], b0h, b1h);
            }
        }
        asm volatile("cp.async.wait_group 0;");
        __syncthreads();
    }

    #pragma unroll
    for (int mt = 0; mt < 4; mt++) {
        #pragma unroll
        for (int nt = 0; nt < 4; nt++) {
            int row = bm + wm*64 + mt*16 + gid;
            int col = bn + wn*32 + nt*8 + qid*2;
            float v00 = c[mt][nt][0], v01 = c[mt][nt][1];
            float v10 = c[mt][nt][2], v11 = c[mt][nt][3];
            if (EPI == 1) {
                float b0v = bias[col], b1v = bias[col+1];
                float g00 = gelu_fast(v00 + b0v), g01 = gelu_fast(v01 + b1v);
                float g10 = gelu_fast(v10 + b0v), g11 = gelu_fast(v11 + b1v);
                unsigned h0, l0, h1, l1;
                split_pair(g00, g01, h0, l0);
                split_pair(g10, g11, h1, l1);
                int wcol = col >> 1;
                Ch[(size_t)row*(Nld>>1) + wcol]     = h0;
                Cl[(size_t)row*(Nld>>1) + wcol]     = l0;
                Ch[(size_t)(row+8)*(Nld>>1) + wcol] = h1;
                Cl[(size_t)(row+8)*(Nld>>1) + wcol] = l1;
            } else {
                float* p0 = Cu + (size_t)row*Nld + col;
                float* p1 = Cu + (size_t)(row+8)*Nld + col;
                if (EPI == 0) {
                    p0[0] = v00; p0[1] = v01; p1[0] = v10; p1[1] = v11;
                } else if (EPI == 3) {
                    p0[0] += v00; p0[1] += v01; p1[0] += v10; p1[1] += v11;
                } else {
                    float b0v = bias[col], b1v = bias[col+1];
                    p0[0] += v00 + b0v; p0[1] += v01 + b1v;
                    p1[0] += v10 + b0v; p1[1] += v11 + b1v;
                }
            }
        }
    }
}

// ---------------- LSH hashing: 2 tokens/thread, shared rot reads ----------------
__global__ void hash_kernel(const float* __restrict__ rot,
                            const float* __restrict__ qk, int* __restrict__ bkt) {
    __shared__ float rs[64*64];
    __shared__ float sq[64][68];
    int blk = blockIdx.x;
    int bh = blk >> 4;
    int t0 = (blk & 15)*64;
    int b = bh >> 3, h = bh & 7;
    int tid = threadIdx.x;
    for (int i = tid; i < 64*64; i += 256) rs[i] = rot[i];
    for (int i = tid; i < 64*16; i += 256) {
        int r = i >> 4, c4 = (i & 15)*4;
        float4 q4 = *(const float4*)&qk[(size_t)(b*Tt + t0 + r)*Dd + h*DHh + c4];
        sq[r][c4+0] = q4.x; sq[r][c4+1] = q4.y; sq[r][c4+2] = q4.z; sq[r][c4+3] = q4.w;
    }
    __syncthreads();
    int tl = tid >> 3;
    int nh = tid & 7;
    float rv[8], rw[8];
    #pragma unroll
    for (int r = 0; r < 8; r++) { rv[r] = 0.f; rw[r] = 0.f; }
    #pragma unroll 4
    for (int d = 0; d < 64; d++) {
        float q1 = sq[tl][d];
        float q2 = sq[tl+32][d];
        float4 r0 = *(const float4*)&rs[d*64 + nh*8];
        float4 r1 = *(const float4*)&rs[d*64 + nh*8 + 4];
        rv[0] += q1*r0.x; rv[1] += q1*r0.y; rv[2] += q1*r0.z; rv[3] += q1*r0.w;
        rv[4] += q1*r1.x; rv[5] += q1*r1.y; rv[6] += q1*r1.z; rv[7] += q1*r1.w;
        rw[0] += q2*r0.x; rw[1] += q2*r0.y; rw[2] += q2*r0.z; rw[3] += q2*r0.w;
        rw[4] += q2*r1.x; rw[5] += q2*r1.y; rw[6] += q2*r1.z; rw[7] += q2*r1.w;
    }
    {
        int best = 0; float bv = rv[0];
        #pragma unroll
        for (int r = 1; r < 8; r++) if (rv[r] > bv) { bv = rv[r]; best = r; }
        #pragma unroll
        for (int r = 0; r < 8; r++) { float nv = -rv[r]; if (nv > bv) { bv = nv; best = 8 + r; } }
        bkt[(bh*NHh + nh)*Tt + t0 + tl] = best;
    }
    {
        int best = 0; float bv = rw[0];
        #pragma unroll
        for (int r = 1; r < 8; r++) if (rw[r] > bv) { bv = rw[r]; best = r; }
        #pragma unroll
        for (int r = 0; r < 8; r++) { float nv = -rw[r]; if (nv > bv) { bv = nv; best = 8 + r; } }
        bkt[(bh*NHh + nh)*Tt + t0 + tl + 32] = best;
    }
}

// ---------------- stable counting sort ----------------
__global__ void sort_kernel(const int* __restrict__ bkt, int* __restrict__ st) {
    __shared__ int sb[Tt];
    __shared__ int cnt[16];
    __shared__ int off[16];
    int base = blockIdx.x*Tt;
    int tid = threadIdx.x;
    for (int i = tid; i < Tt; i += 512) sb[i] = bkt[base + i];
    __syncthreads();
    int w = tid >> 5, lane = tid & 31;
    int c = 0;
    for (int it = 0; it < 32; it++) {
        unsigned m = __ballot_sync(0xffffffffu, sb[it*32 + lane] == w);
        c += __popc(m);
    }
    if (lane == 0) cnt[w] = c;
    __syncthreads();
    if (tid == 0) {
        int s = 0;
        for (int i = 0; i < 16; i++) { off[i] = s; s += cnt[i]; }
    }
    __syncthreads();
    int p = off[w];
    for (int it = 0; it < 32; it++) {
        int t = it*32 + lane;
        int bb = sb[t];
        unsigned m = __ballot_sync(0xffffffffu, bb == w);
        if (bb == w) {
            int pos = p + __popc(m & ((1u << lane) - 1u));
            st[base + pos] = t;
        }
        p += __popc(m);
    }
}

// ---------------- chunked LSH attention (3-term bf16 k16, packed-pair tiles) ----------------
__global__ void __launch_bounds__(256,2) attn_kernel(const int* __restrict__ st,
                                                   const float* __restrict__ qk,
                                                   const float* __restrict__ vg,
                                                   float* __restrict__ slog,
                                                   float* __restrict__ bo) {
    extern __shared__ float sm[];
    unsigned* qh = (unsigned*)sm;
    unsigned* ql = qh + 64*PIT;
    unsigned* kh = ql + 64*PIT;
    unsigned* kl = kh + 64*PIT;
    float* sd   = (float*)(kl + 64*PIT);
    float* invs = sd + 64*132;
    int*   posK = (int*)(invs + 128);

    int n = blockIdx.x, bh = blockIdx.y;
    int b = bh >> 3, h = bh & 7;
    int tid = threadIdx.x;
    int nh = n >> 4;
    int segb = bh*SEG;

    const int lane = tid & 31, warp = tid >> 5;
    const int gid = lane >> 2, qid = lane & 3;

    if (tid < 128) {
        int cc = (tid < 64) ? n : ((n + NC - 1) & (NC-1));
        posK[tid] = st[segb + cc*BSz + (tid & 63)];
    }
    __syncthreads();

    for (int i = tid; i < 64*16; i += 256) {
        int r = i >> 4, c4 = (i & 15)*4;
        int wp = c4 >> 1;
        float4 a = *(const float4*)&qk[(size_t)(b*Tt + posK[r])*Dd + h*DHh + c4];
        unsigned h0, l0, h1, l1;
        split_pair(a.x, a.y, h0, l0); split_pair(a.z, a.w, h1, l1);
        qh[r*PIT + wp] = h0; qh[r*PIT + wp+1] = h1;
        ql[r*PIT + wp] = l0; ql[r*PIT + wp+1] = l1;
        float4 k2 = *(const float4*)&qk[(size_t)(b*Tt + posK[64+r])*Dd + h*DHh + c4];
        split_pair(k2.x, k2.y, h0, l0); split_pair(k2.z, k2.w, h1, l1);
        kh[r*PIT + wp] = h0; kh[r*PIT + wp+1] = h1;
        kl[r*PIT + wp] = l0; kl[r*PIT + wp+1] = l1;
    }
    __syncthreads();

    if (tid < 128) {
        const unsigned* ph = (tid < 64) ? qh : kh;
        const unsigned* pl = (tid < 64) ? ql : kl;
        int r = tid & 63;
        float s = 0.f;
        #pragma unroll 8
        for (int w = 0; w < 32; w++) {
            unsigned hw = ph[r*PIT + w], lw = pl[r*PIT + w];
            float x0 = __uint_as_float(hw << 16) + __uint_as_float(lw << 16);
            float x1 = __uint_as_float(hw & 0xffff0000u) + __uint_as_float(lw & 0xffff0000u);
            s += x0*x0 + x1*x1;
        }
        invs[tid] = 1.f/(sqrtf(s) + 1e-8f);
    }
    __syncthreads();

    {
        const int mb  = (warp & 1)*32;
        const int khh = (warp >> 1) & 1;
        const int nb  = (warp >> 2)*32;
        const unsigned* bhp = khh ? kh : qh;
        const unsigned* blp = khh ? kl : ql;
        float c[2][4][4];
        #pragma unroll
        for (int mt = 0; mt < 2; mt++)
            #pragma unroll
            for (int nt = 0; nt < 4; nt++)
                #pragma unroll
                for (int e = 0; e < 4; e++) c[mt][nt][e] = 0.f;

        #pragma unroll
        for (int kt = 0; kt < 4; kt++) {
            int kw = kt*8;
            unsigned ah[2][4], al[2][4];
            #pragma unroll
            for (int mt = 0; mt < 2; mt++) {
                int r0 = (mb + mt*16 + gid)*PIT;
                int r1 = r0 + 8*PIT;
                ah[mt][0] = qh[r0 + kw+qid];   al[mt][0] = ql[r0 + kw+qid];
                ah[mt][1] = qh[r1 + kw+qid];   al[mt][1] = ql[r1 + kw+qid];
                ah[mt][2] = qh[r0 + kw+qid+4]; al[mt][2] = ql[r0 + kw+qid+4];
                ah[mt][3] = qh[r1 + kw+qid+4]; al[mt][3] = ql[r1 + kw+qid+4];
            }
            #pragma unroll
            for (int nt = 0; nt < 4; nt++) {
                int kr = (nb + nt*8 + gid)*PIT;
                unsigned b0h = bhp[kr + kw+qid],   b0l = blp[kr + kw+qid];
                unsigned b1h = bhp[kr + kw+qid+4], b1l = blp[kr + kw+qid+4];
                #pragma unroll
                for (int mt = 0; mt < 2; mt++) {
                    mma_bf16(c[mt][nt], ah[mt][0],ah[mt][1],ah[mt][2],ah[mt][3], b0h, b1h);
                    mma_bf16(c[mt][nt], ah[mt][0],ah[mt][1],ah[mt][2],ah[mt][3], b0l, b1l);
                    mma_bf16(c[mt][nt], al[mt][0],al[mt][1],al[mt][2],al[mt][3], b0h, b1h);
                }
            }
        }
        #pragma unroll
        for (int mt = 0; mt < 2; mt++) {
            int r0 = mb + mt*16 + gid;
            int pq0 = posK[r0], pq1 = posK[r0+8];
            #pragma unroll
            for (int nt = 0; nt < 4; nt++) {
                int col = khh*64 + nb + nt*8 + qid*2;
                float is0 = invs[col]*0.125f, is1 = invs[col+1]*0.125f;
                int pk0 = posK[col], pk1 = posK[col+1];
                float s00 = c[mt][nt][0]*is0; if (pq0 == pk0) s00 = -5e4f;
                float s01 = c[mt][nt][1]*is1; if (pq0 == pk1) s01 = -5e4f;
                float s10 = c[mt][nt][2]*is0; if (pq1 == pk0) s10 = -5e4f;
                float s11 = c[mt][nt][3]*is1; if (pq1 == pk1) s11 = -5e4f;
                sd[r0*132 + col] = s00;     sd[r0*132 + col+1] = s01;
                sd[(r0+8)*132 + col] = s10; sd[(r0+8)*132 + col+1] = s11;
            }
        }
    }
    __syncthreads();

    {
        int r = tid >> 2, c4 = tid & 3;
        float vals[32];
        float mx = -1e30f;
        #pragma unroll
        for (int i = 0; i < 32; i++) { vals[i] = sd[r*132 + i*4 + c4]; mx = fmaxf(mx, vals[i]); }
        mx = fmaxf(mx, __shfl_xor_sync(0xffffffffu, mx, 1));
        mx = fmaxf(mx, __shfl_xor_sync(0xffffffffu, mx, 2));
        float se = 0.f;
        #pragma unroll
        for (int i = 0; i < 32; i++) { vals[i] = __expf(vals[i] - mx); se += vals[i]; }
        se += __shfl_xor_sync(0xffffffffu, se, 1);
        se += __shfl_xor_sync(0xffffffffu, se, 2);
        if (c4 == 0) slog[((size_t)bh*NHh + nh)*Tt + posK[r]] = mx + __logf(se);
        float inv_se = 1.f/se;
        #pragma unroll
        for (int i = 0; i < 32; i++) sd[r*132 + i*4 + c4] = vals[i]*inv_se;
    }
    __syncthreads();

    for (int i = tid; i < 1024; i += 256) {
        int half = i >> 9;
        int p  = (i >> 4) & 31;
        int d4 = (i & 15)*4;
        unsigned* vh = half ? kh : qh;
        unsigned* vl = half ? kl : ql;
        float4 a0 = *(const float4*)&vg[(size_t)(b*Tt + posK[half*64 + 2*p  ])*Dd + h*DHh + d4];
        float4 a1 = *(const float4*)&vg[(size_t)(b*Tt + posK[half*64 + 2*p+1])*Dd + h*DHh + d4];
        unsigned hw, lw;
        split_pair(a0.x, a1.x, hw, lw); vh[(d4+0)*PIT + p] = hw; vl[(d4+0)*PIT + p] = lw;
        split_pair(a0.y, a1.y, hw, lw); vh[(d4+1)*PIT + p] = hw; vl[(d4+1)*PIT + p] = lw;
        split_pair(a0.z, a1.z, hw, lw); vh[(d4+2)*PIT + p] = hw; vl[(d4+2)*PIT + p] = lw;
        split_pair(a0.w, a1.w, hw, lw); vh[(d4+3)*PIT + p] = hw; vl[(d4+3)*PIT + p] = lw;
    }
    __syncthreads();

    {
        const int mb = (warp & 1)*32;
        const int db = ((warp >> 1) & 3)*16;
        float c[2][2][4];
        #pragma unroll
        for (int mt = 0; mt < 2; mt++)
            #pragma unroll
            for (int nt = 0; nt < 2; nt++)
                #pragma unroll
                for (int e = 0; e < 4; e++) c[mt][nt][e] = 0.f;

        #pragma unroll
        for (int kt = 0; kt < 8; kt++) {
            int k0 = kt*16;
            const unsigned* vh = (kt < 4) ? qh : kh;
            const unsigned* vl = (kt < 4) ? ql : kl;
            int kw = (kt & 3)*8;
            unsigned ah[2][4], al[2][4];
            #pragma unroll
            for (int mt = 0; mt < 2; mt++) {
                int r0 = (mb + mt*16 + gid)*132;
                int r1 = r0 + 8*132;
                split_pair(sd[r0 + k0+2*qid],   sd[r0 + k0+2*qid+1],   ah[mt][0], al[mt][0]);
                split_pair(sd[r1 + k0+2*qid],   sd[r1 + k0+2*qid+1],   ah[mt][1], al[mt][1]);
                split_pair(sd[r0 + k0+2*qid+8], sd[r0 + k0+2*qid+9],   ah[mt][2], al[mt][2]);
                split_pair(sd[r1 + k0+2*qid+8], sd[r1 + k0+2*qid+9],   ah[mt][3], al[mt][3]);
            }
            #pragma unroll
            for (int nt = 0; nt < 2; nt++) {
                int d = db + nt*8 + gid;
                unsigned b0h = vh[d*PIT + kw + qid],   b0l = vl[d*PIT + kw + qid];
                unsigned b1h = vh[d*PIT + kw + qid+4], b1l = vl[d*PIT + kw + qid+4];
                #pragma unroll
                for (int mt = 0; mt < 2; mt++) {
                    mma_bf16(c[mt][nt], ah[mt][0],ah[mt][1],ah[mt][2],ah[mt][3], b0h, b1h);
                    mma_bf16(c[mt][nt], ah[mt][0],ah[mt][1],ah[mt][2],ah[mt][3], b0l, b1l);
                    mma_bf16(c[mt][nt], al[mt][0],al[mt][1],al[mt][2],al[mt][3], b0h, b1h);
                }
            }
        }
        size_t base0 = ((size_t)bh*NHh + nh)*Tt;
        #pragma unroll
        for (int mt = 0; mt < 2; mt++) {
            int r0 = mb + mt*16 + gid;
            float* bo0 = &bo[(base0 + posK[r0])*DHh];
            float* bo1 = &bo[(base0 + posK[r0+8])*DHh];
            #pragma unroll
            for (int nt = 0; nt < 2; nt++) {
                int col = db + nt*8 + qid*2;
                bo0[col] = c[mt][nt][0]; bo0[col+1] = c[mt][nt][1];
                bo1[col] = c[mt][nt][2]; bo1[col+1] = c[mt][nt][3];
            }
        }
    }
}

// ---------------- combine: writes packed hi/lo ao ----------------
__global__ void combine_kernel(const float* __restrict__ slog,
                               const float* __restrict__ bo,
                               unsigned* __restrict__ aoh, unsigned* __restrict__ aol) {
    int idx = blockIdx.x*256 + threadIdx.x;
    if (idx >= BHn*Tt*16) return;
    int d4 = (idx & 15)*4;
    int t  = (idx >> 4) & (Tt-1);
    int bh = idx >> 14;
    float lg[NHh];
    float mx = -1e30f;
    #pragma unroll
    for (int i = 0; i < NHh; i++) {
        lg[i] = slog[((size_t)bh*NHh + i)*Tt + t];
        mx = fmaxf(mx, lg[i]);
    }
    float se = 0.f;
    #pragma unroll
    for (int i = 0; i < NHh; i++) { lg[i] = __expf(lg[i] - mx); se += lg[i]; }
    float inv = 1.f/se;
    float4 out = make_float4(0.f, 0.f, 0.f, 0.f);
    #pragma unroll
    for (int i = 0; i < NHh; i++) {
        float w = lg[i]*inv;
        float4 bv = *(const float4*)&bo[(((size_t)bh*NHh + i)*Tt + t)*DHh + d4];
        out.x += w*bv.x; out.y += w*bv.y; out.z += w*bv.z; out.w += w*bv.w;
    }
    int b = bh >> 3, h = bh & 7;
    unsigned h0, l0, h1, l1;
    split_pair(out.x, out.y, h0, l0);
    split_pair(out.z, out.w, h1, l1);
    size_t base = (size_t)(b*Tt + t)*256 + ((h*DHh + d4) >> 1);
    aoh[base] = h0; aoh[base+1] = h1;
    aol[base] = l0; aol[base+1] = l1;
}

// ---------------- pooling (reads split xn) + fc ----------------
__global__ void pool_kernel(const unsigned* __restrict__ xh, const unsigned* __restrict__ xl,
                            float* __restrict__ pool) {
    int b = blockIdx.x, d = threadIdx.x;
    int w = d >> 1, part = d & 1;
    float s = 0.f;
    for (int t = 0; t < Tt; t++) {
        unsigned hw = xh[(size_t)(b*Tt + t)*256 + w];
        unsigned lw = xl[(size_t)(b*Tt + t)*256 + w];
        float xv;
        if (part) xv = __uint_as_float(hw & 0xffff0000u) + __uint_as_float(lw & 0xffff0000u);
        else      xv = __uint_as_float(hw << 16) + __uint_as_float(lw << 16);
        s += xv;
    }
    pool[b*Dd + d] = s * (1.f/(float)Tt);
}

__global__ void fc_kernel(const float* __restrict__ pool,
                          const float* __restrict__ Wfc, float* __restrict__ out) {
    int b = blockIdx.x, n = threadIdx.x;
    float s = 0.f;
    for (int kk = 0; kk < Dd; kk++) s += pool[b*Dd + kk]*Wfc[kk*Dd + n];
    out[b*Dd + n] = s;
}

// ---------------- orchestration ----------------
extern "C" void kernel_launch(void* const* d_in, const int* in_sizes, int n_in,
                              void* d_out, int out_size) {
    const int*   ids = (const int*)  d_in[0];
    const float* tok = (const float*)d_in[1];
    const float* pos = (const float*)d_in[2];
    const float* lag = (const float*)d_in[3];
    const float* lab = (const float*)d_in[4];
    const float* Wqk = (const float*)d_in[5];
    const float* Wv  = (const float*)d_in[6];
    const float* Wo  = (const float*)d_in[7];
    const float* lfg = (const float*)d_in[8];
    const float* lfb = (const float*)d_in[9];
    const float* W1  = (const float*)d_in[10];
    const float* b1  = (const float*)d_in[11];
    const float* W2  = (const float*)d_in[12];
    const float* b2  = (const float*)d_in[13];
    const float* lng = (const float*)d_in[14];
    const float* lnb = (const float*)d_in[15];
    const float* Wfc = (const float*)d_in[16];
    const float* rot = (const float*)d_in[17];
    float* out = (float*)d_out;

    float *x1, *x2, *qk, *v, *bo, *slog, *pool;
    int *st, *bkt;
    unsigned *xnh, *xnl, *ffhh, *ffhl, *aoh, *aol;
    unsigned *wqkh, *wqkl, *wvh, *wvl, *woh, *wol, *w1h, *w1l, *w2h, *w2l;
    cudaGetSymbolAddress((void**)&x1,   g_x1);
    cudaGetSymbolAddress((void**)&x2,   g_x2);
    cudaGetSymbolAddress((void**)&qk,   g_qk);
    cudaGetSymbolAddress((void**)&v,    g_v);
    cudaGetSymbolAddress((void**)&bo,   g_bo);
    cudaGetSymbolAddress((void**)&slog, g_slog);
    cudaGetSymbolAddress((void**)&pool, g_pool);
    cudaGetSymbolAddress((void**)&st,   g_st);
    cudaGetSymbolAddress((void**)&bkt,  g_bkt);
    cudaGetSymbolAddress((void**)&xnh,  g_xnh);
    cudaGetSymbolAddress((void**)&xnl,  g_xnl);
    cudaGetSymbolAddress((void**)&ffhh, g_ffhh);
    cudaGetSymbolAddress((void**)&ffhl, g_ffhl);
    cudaGetSymbolAddress((void**)&aoh,  g_aoh);
    cudaGetSymbolAddress((void**)&aol,  g_aol);
    cudaGetSymbolAddress((void**)&wqkh, g_WqkH);
    cudaGetSymbolAddress((void**)&wqkl, g_WqkL);
    cudaGetSymbolAddress((void**)&wvh,  g_WvH);
    cudaGetSymbolAddress((void**)&wvl,  g_WvL);
    cudaGetSymbolAddress((void**)&woh,  g_WoH);
    cudaGetSymbolAddress((void**)&wol,  g_WoL);
    cudaGetSymbolAddress((void**)&w1h,  g_W1H);
    cudaGetSymbolAddress((void**)&w1l,  g_W1L);
    cudaGetSymbolAddress((void**)&w2h,  g_W2H);
    cudaGetSymbolAddress((void**)&w2l,  g_W2L);

    const int ATTN_SMEM = 4*64*PIT*4 + 64*132*4 + 128*4 + 128*4;   // 71680
    cudaFuncSetAttribute(attn_kernel, cudaFuncAttributeMaxDynamicSharedMemorySize, ATTN_SMEM);

    const int M = Bb*Tt;

    // pre-split all weights into bf16 hi/lo pair-packed buffers
    convw_kernel<<<(DEPTHL*256*512 + 255)/256, 256>>>(Wqk, wqkh, wqkl, DEPTHL*256, 512);
    convw_kernel<<<(DEPTHL*256*512 + 255)/256, 256>>>(Wv,  wvh,  wvl,  DEPTHL*256, 512);
    convw_kernel<<<(DEPTHL*256*512 + 255)/256, 256>>>(Wo,  woh,  wol,  DEPTHL*256, 512);
    convw_kernel<<<(DEPTHL*256*2048 + 255)/256, 256>>>(W1, w1h, w1l, DEPTHL*256, 2048);
    convw_kernel<<<(DEPTHL*1024*512 + 255)/256, 256>>>(W2, w2h, w2l, DEPTHL*1024, 512);

    embed_kernel<<<(Bb*Tt*Dd + 255)/256, 256>>>(ids, tok, pos, x1, x2);

    for (int l = 0; l < DEPTHL; l++) {
        const unsigned* wqkh_l = wqkh + (size_t)l*256*512;
        const unsigned* wqkl_l = wqkl + (size_t)l*256*512;
        const unsigned* wvh_l  = wvh  + (size_t)l*256*512;
        const unsigned* wvl_l  = wvl  + (size_t)l*256*512;
        const unsigned* woh_l  = woh  + (size_t)l*256*512;
        const unsigned* wol_l  = wol  + (size_t)l*256*512;
        const unsigned* w1h_l  = w1h  + (size_t)l*256*2048;
        const unsigned* w1l_l  = w1l  + (size_t)l*256*2048;
        const unsigned* w2h_l  = w2h  + (size_t)l*1024*512;
        const unsigned* w2l_l  = w2l  + (size_t)l*1024*512;
        const float* b1_l  = b1  + (size_t)l*FFf;
        const float* b2_l  = b2  + (size_t)l*Dd;
        const float* rot_l = rot + (size_t)l*DHh*64;

        // attention block: x1 += attn(LN(x2)) @ Wo
        ln_kernel<<<M, 256>>>(x2, nullptr, xnh, xnl, lag + l*Dd, lab + l*Dd);
        gemm_kernel<0><<<dim3(1024/128, M/128), 256>>>(xnh, xnl, wqkh_l, wqkl_l,
            nullptr, qk, nullptr, nullptr, M, Dd, wvh_l, wvl_l, v, Dd, Dd);
        hash_kernel<<<BHn*16, 256>>>(rot_l, qk, bkt);
        sort_kernel<<<BHn*NHh, 512>>>(bkt, st);
        attn_kernel<<<dim3(NC, BHn), 256, ATTN_SMEM>>>(st, qk, v, slog, bo);
        combine_kernel<<<(BHn*Tt*16)/256, 256>>>(slog, bo, aoh, aol);
        gemm_kernel<3><<<dim3(Dd/128, M/128), 256>>>(aoh, aol, woh_l, wol_l,
            nullptr, x1, nullptr, nullptr, M, Dd, nullptr, nullptr, nullptr, 0, Dd);

        // feed-forward block: x2 += gelu(LN(x1)@W1 + b1) @ W2 + b2
        ln_kernel<<<M, 256>>>(x1, nullptr, xnh, xnl, lfg + l*Dd, lfb + l*Dd);
        gemm_kernel<1><<<dim3(FFf/128, M/128), 256>>>(xnh, xnl, w1h_l, w1l_l,
            b1_l, nullptr, ffhh, ffhl, M, Dd, nullptr, nullptr, nullptr, 0, FFf);
        gemm_kernel<4><<<dim3(Dd/128, M/128), 256>>>(ffhh, ffhl, w2h_l, w2l_l,
            b2_l, x2, nullptr, nullptr, M, FFf, nullptr, nullptr, nullptr, 0, Dd);
    }

    // final: 0.5*(x1+x2) -> LN -> mean over T -> @ Wfc
    ln_kernel<<<M, 256>>>(x1, x2, xnh, xnl, lng, lnb);
    pool_kernel<<<Bb, Dd>>>(xnh, xnl, pool);
    fc_kernel<<<Bb, Dd>>>(pool, Wfc, out);
}

// round 17
// speedup vs baseline: 1.0060x; 1.0060x over previous
#include <cuda_runtime.h>
#include <math.h>
#include <stdint.h>

#define Bb 8
#define Tt 1024
#define Dd 512
#define Hh 8
#define DHh 64
#define DEPTHL 8
#define FFf 2048
#define NHh 8
#define BSz 64
#define NBk 16
#define NC (NHh*NBk)
#define BHn (Bb*Hh)
#define SEG (NHh*Tt)

#define PIT 36   // attention packed-pair row pitch (words)

// ---------------- scratch ----------------
__device__ float g_x1[Bb*Tt*Dd];
__device__ float g_x2[Bb*Tt*Dd];
__device__ float g_qk[Bb*Tt*Dd];
__device__ float g_v [Bb*Tt*Dd];
__device__ float g_bo[(size_t)BHn*NHh*Tt*DHh];
__device__ float g_slog[BHn*NHh*Tt];
__device__ int   g_st [BHn*SEG];
__device__ int   g_bkt[BHn*SEG];
__device__ float g_pool[Bb*Dd];
// packed bf16 hi/lo activations (pair along feature dim)
__device__ unsigned g_xnh[Bb*Tt*Dd/2],  g_xnl[Bb*Tt*Dd/2];
__device__ unsigned g_ffhh[Bb*Tt*FFf/2], g_ffhl[Bb*Tt*FFf/2];
__device__ unsigned g_aoh[Bb*Tt*Dd/2],  g_aol[Bb*Tt*Dd/2];
// packed bf16 hi/lo weights (pair along K dim): [K/2][N] words per layer
__device__ unsigned g_WqkH[DEPTHL*256*512], g_WqkL[DEPTHL*256*512];
__device__ unsigned g_WvH [DEPTHL*256*512], g_WvL [DEPTHL*256*512];
__device__ unsigned g_WoH [DEPTHL*256*512], g_WoL [DEPTHL*256*512];
__device__ unsigned g_W1H [DEPTHL*256*2048], g_W1L [DEPTHL*256*2048];
__device__ unsigned g_W2H [DEPTHL*1024*512], g_W2L [DEPTHL*1024*512];

// ---------------- helpers ----------------
__device__ __forceinline__ float gelu_fast(float x) {
    float u = 0.7978845608028654f*(x + 0.044715f*x*x*x);
    float t = 1.f - 2.f/(__expf(2.f*u) + 1.f);
    return 0.5f*x*(1.f + t);
}

__device__ __forceinline__ float blockReduceSum256(float val, float* red) {
    #pragma unroll
    for (int o = 16; o; o >>= 1) val += __shfl_xor_sync(0xffffffffu, val, o);
    int w = threadIdx.x >> 5;
    if ((threadIdx.x & 31) == 0) red[w] = val;
    __syncthreads();
    float r = (threadIdx.x < 8) ? red[threadIdx.x] : 0.f;
    if (threadIdx.x < 32) {
        #pragma unroll
        for (int o = 4; o; o >>= 1) r += __shfl_xor_sync(0xffffffffu, r, o);
        if (threadIdx.x == 0) red[0] = r;
    }
    __syncthreads();
    float out = red[0];
    __syncthreads();
    return out;
}

__device__ __forceinline__ void mma_bf16(float* c,
    unsigned a0, unsigned a1, unsigned a2, unsigned a3,
    unsigned b0, unsigned b1) {
    asm volatile(
        "mma.sync.aligned.m16n8k16.row.col.f32.bf16.bf16.f32 "
        "{%0,%1,%2,%3}, {%4,%5,%6,%7}, {%8,%9}, {%0,%1,%2,%3};"
        : "+f"(c[0]), "+f"(c[1]), "+f"(c[2]), "+f"(c[3])
        : "r"(a0), "r"(a1), "r"(a2), "r"(a3), "r"(b0), "r"(b1));
}

// split (x0,x1) into packed bf16x2 hi and lo (residual); x0 in low half.
__device__ __forceinline__ void split_pair(float x0, float x1,
                                           unsigned &hi, unsigned &lo) {
    unsigned h;
    asm("cvt.rn.bf16x2.f32 %0, %1, %2;" : "=r"(h) : "f"(x1), "f"(x0));
    float h0 = __uint_as_float(h << 16);
    float h1 = __uint_as_float(h & 0xffff0000u);
    float l0 = x0 - h0, l1 = x1 - h1;
    asm("cvt.rn.bf16x2.f32 %0, %1, %2;" : "=r"(lo) : "f"(l1), "f"(l0));
    hi = h;
}

__device__ __forceinline__ void cp16(void* smem, const void* gmem) {
    unsigned s = (unsigned)__cvta_generic_to_shared(smem);
    asm volatile("cp.async.ca.shared.global [%0], [%1], 16;" :: "r"(s), "l"(gmem));
}

// ---------------- weight pre-split: [2*rows2][N] fp32 -> [rows2][N] hi/lo words ----------------
__global__ void convw_kernel(const float* __restrict__ W,
                             unsigned* __restrict__ Wh, unsigned* __restrict__ Wl,
                             int rows2, int N) {
    int idx = blockIdx.x*256 + threadIdx.x;
    if (idx >= rows2*N) return;
    int r2 = idx / N, n = idx - r2*N;
    float x0 = W[(size_t)(2*r2)*N + n];
    float x1 = W[(size_t)(2*r2+1)*N + n];
    unsigned h, l;
    split_pair(x0, x1, h, l);
    Wh[idx] = h; Wl[idx] = l;
}

// ---------------- embedding ----------------
__global__ void embed_kernel(const int* __restrict__ ids,
                             const float* __restrict__ tok,
                             const float* __restrict__ pos,
                             float* __restrict__ x1, float* __restrict__ x2) {
    int i = blockIdx.x*256 + threadIdx.x;
    if (i >= Bb*Tt*Dd) return;
    int d = i & (Dd-1);
    int bt = i >> 9;
    int t = bt & (Tt-1);
    int id = ids[bt];
    if (id < 0) id = 0;
    if (id >= 6400) id = 6399;
    float v = tok[(size_t)id*Dd + d] + pos[t*Dd + d];
    x1[i] = v; x2[i] = v;
}

// ---------------- layernorm: emits packed hi/lo pairs ----------------
__global__ void ln_kernel(const float* __restrict__ x, const float* __restrict__ xb,
                          unsigned* __restrict__ yh, unsigned* __restrict__ yl,
                          const float* __restrict__ g, const float* __restrict__ bia) {
    __shared__ float red[8];
    int row = blockIdx.x;
    int i = threadIdx.x;                     // pair index 0..255
    float2 xv = *(const float2*)&x[(size_t)row*Dd + 2*i];
    float v0 = xv.x, v1 = xv.y;
    if (xb) {
        float2 bv = *(const float2*)&xb[(size_t)row*Dd + 2*i];
        v0 = 0.5f*(v0 + bv.x); v1 = 0.5f*(v1 + bv.y);
    }
    float s = blockReduceSum256(v0+v1, red);
    float mean = s * (1.f/512.f);
    float d0 = v0 - mean, d1 = v1 - mean;
    float s2 = blockReduceSum256(d0*d0 + d1*d1, red);
    float inv = rsqrtf(s2*(1.f/512.f) + 1e-5f);
    float2 gv = *(const float2*)&g[2*i];
    float2 bb = *(const float2*)&bia[2*i];
    float y0 = d0*inv*gv.x + bb.x;
    float y1 = d1*inv*gv.y + bb.y;
    unsigned h, l;
    split_pair(y0, y1, h, l);
    yh[(size_t)row*256 + i] = h;
    yl[(size_t)row*256 + i] = l;
}

// ---------------- tensor-core GEMM: pre-split bf16 operands, 2 CTAs/SM ----------------
// A: packed [M][K/2] hi/lo; B: packed [K/2][N] hi/lo.
// EPI: 0 = store fp32, 1 = gelu(acc+bias) -> split store, 3 = Cf += acc, 4 = Cf += acc + bias
template<int EPI>
__global__ void __launch_bounds__(256, 2) gemm_kernel(
        const unsigned* __restrict__ Ah, const unsigned* __restrict__ Al,
        const unsigned* __restrict__ Bh0, const unsigned* __restrict__ Bl0,
        const float* __restrict__ bias,
        float* __restrict__ Cf, unsigned* __restrict__ Ch, unsigned* __restrict__ Cl,
        int M, int K,
        const unsigned* __restrict__ B2h, const unsigned* __restrict__ B2l,
        float* __restrict__ C2f,
        int nHalf, int Nplain) {
    __shared__ unsigned AsH[2][128][12], AsL[2][128][12];
    __shared__ unsigned BsH[2][8][132],  BsL[2][8][132];

    const int tid  = threadIdx.x;
    const int lane = tid & 31;
    const int warp = tid >> 5;
    const int wm = warp & 1;
    const int wn = warp >> 1;
    const int gid = lane >> 2;
    const int qid = lane & 3;
    const int bm = blockIdx.y*128;

    const unsigned* Buh = Bh0;
    const unsigned* Bul = Bl0;
    float* Cu = Cf;
    int bn = blockIdx.x*128;
    int Nld = Nplain;
    if (B2h != nullptr) {
        Nld = nHalf;
        if (bn >= nHalf) { Buh = B2h; Bul = B2l; Cu = C2f; bn -= nHalf; }
    }
    const int K2 = K >> 1;

    float c[4][4][4];
    #pragma unroll
    for (int mt = 0; mt < 4; mt++)
        #pragma unroll
        for (int nt = 0; nt < 4; nt++)
            #pragma unroll
            for (int e = 0; e < 4; e++) c[mt][nt][e] = 0.f;

    const int ar = tid >> 1, aw = (tid & 1)*4;   // A: row 0..127, word 0 or 4
    const int br = tid >> 5, bc = (tid & 31)*4;  // B: k-pair row 0..7, col-word

    const int nk = K >> 4;

    {
        cp16(&AsH[0][ar][aw], Ah + (size_t)(bm + ar)*K2 + aw);
        cp16(&AsL[0][ar][aw], Al + (size_t)(bm + ar)*K2 + aw);
        cp16(&BsH[0][br][bc], Buh + (size_t)br*Nld + bn + bc);
        cp16(&BsL[0][br][bc], Bul + (size_t)br*Nld + bn + bc);
        asm volatile("cp.async.commit_group;");
        asm volatile("cp.async.wait_group 0;");
    }
    __syncthreads();

    for (int kt = 0; kt < nk; kt++) {
        const int cur = kt & 1;
        if (kt + 1 < nk) {
            const int nxt = cur ^ 1;
            int k8 = (kt + 1)*8;               // pair-word offset
            cp16(&AsH[nxt][ar][aw], Ah + (size_t)(bm + ar)*K2 + k8 + aw);
            cp16(&AsL[nxt][ar][aw], Al + (size_t)(bm + ar)*K2 + k8 + aw);
            cp16(&BsH[nxt][br][bc], Buh + (size_t)(k8 + br)*Nld + bn + bc);
            cp16(&BsL[nxt][br][bc], Bul + (size_t)(k8 + br)*Nld + bn + bc);
            asm volatile("cp.async.commit_group;");
        }

        unsigned ah[4][4], alr[4][4];
        #pragma unroll
        for (int mt = 0; mt < 4; mt++) {
            int r0 = wm*64 + mt*16 + gid;
            ah[mt][0] = AsH[cur][r0  ][qid];   alr[mt][0] = AsL[cur][r0  ][qid];
            ah[mt][1] = AsH[cur][r0+8][qid];   alr[mt][1] = AsL[cur][r0+8][qid];
            ah[mt][2] = AsH[cur][r0  ][qid+4]; alr[mt][2] = AsL[cur][r0  ][qid+4];
            ah[mt][3] = AsH[cur][r0+8][qid+4]; alr[mt][3] = AsL[cur][r0+8][qid+4];
        }
        #pragma unroll
        for (int nt = 0; nt < 4; nt++) {
            int nc = wn*32 + nt*8 + gid;
            unsigned b0h = BsH[cur][qid  ][nc], b0l = BsL[cur][qid  ][nc];
            unsigned b1h = BsH[cur][qid+4][nc], b1l = BsL[cur][qid+4][nc];
            #pragma unroll
            for (int mt = 0; mt < 4; mt++) {
                mma_bf16(c[mt][nt], ah[mt][0],ah[mt][1],ah[mt][2],ah[mt][3], b0h, b1h);
                mma_bf16(c[mt][nt], ah[mt][0],ah[mt][1],ah[mt][2],ah[mt][3], b0l, b1l);
                mma_bf16(c[mt][nt], alr[mt][0],alr[mt][1],alr[mt][2],alr[mt][3], b0h, b1h);
            }
        }
        asm volatile("cp.async.wait_group 0;");
        __syncthreads();
    }

    #pragma unroll
    for (int mt = 0; mt < 4; mt++) {
        #pragma unroll
        for (int nt = 0; nt < 4; nt++) {
            int row = bm + wm*64 + mt*16 + gid;
            int col = bn + wn*32 + nt*8 + qid*2;
            float v00 = c[mt][nt][0], v01 = c[mt][nt][1];
            float v10 = c[mt][nt][2], v11 = c[mt][nt][3];
            if (EPI == 1) {
                float b0v = bias[col], b1v = bias[col+1];
                float g00 = gelu_fast(v00 + b0v), g01 = gelu_fast(v01 + b1v);
                float g10 = gelu_fast(v10 + b0v), g11 = gelu_fast(v11 + b1v);
                unsigned h0, l0, h1, l1;
                split_pair(g00, g01, h0, l0);
                split_pair(g10, g11, h1, l1);
                int wcol = col >> 1;
                Ch[(size_t)row*(Nld>>1) + wcol]     = h0;
                Cl[(size_t)row*(Nld>>1) + wcol]     = l0;
                Ch[(size_t)(row+8)*(Nld>>1) + wcol] = h1;
                Cl[(size_t)(row+8)*(Nld>>1) + wcol] = l1;
            } else {
                float* p0 = Cu + (size_t)row*Nld + col;
                float* p1 = Cu + (size_t)(row+8)*Nld + col;
                if (EPI == 0) {
                    p0[0] = v00; p0[1] = v01; p1[0] = v10; p1[1] = v11;
                } else if (EPI == 3) {
                    p0[0] += v00; p0[1] += v01; p1[0] += v10; p1[1] += v11;
                } else {
                    float b0v = bias[col], b1v = bias[col+1];
                    p0[0] += v00 + b0v; p0[1] += v01 + b1v;
                    p1[0] += v10 + b0v; p1[1] += v11 + b1v;
                }
            }
        }
    }
}

// ---------------- LSH hashing: 2 tokens/thread, shared rot reads ----------------
__global__ void hash_kernel(const float* __restrict__ rot,
                            const float* __restrict__ qk, int* __restrict__ bkt) {
    __shared__ float rs[64*64];
    __shared__ float sq[64][68];
    int blk = blockIdx.x;
    int bh = blk >> 4;
    int t0 = (blk & 15)*64;
    int b = bh >> 3, h = bh & 7;
    int tid = threadIdx.x;
    for (int i = tid; i < 64*64; i += 256) rs[i] = rot[i];
    for (int i = tid; i < 64*16; i += 256) {
        int r = i >> 4, c4 = (i & 15)*4;
        float4 q4 = *(const float4*)&qk[(size_t)(b*Tt + t0 + r)*Dd + h*DHh + c4];
        sq[r][c4+0] = q4.x; sq[r][c4+1] = q4.y; sq[r][c4+2] = q4.z; sq[r][c4+3] = q4.w;
    }
    __syncthreads();
    int tl = tid >> 3;
    int nh = tid & 7;
    float rv[8], rw[8];
    #pragma unroll
    for (int r = 0; r < 8; r++) { rv[r] = 0.f; rw[r] = 0.f; }
    #pragma unroll 4
    for (int d = 0; d < 64; d++) {
        float q1 = sq[tl][d];
        float q2 = sq[tl+32][d];
        float4 r0 = *(const float4*)&rs[d*64 + nh*8];
        float4 r1 = *(const float4*)&rs[d*64 + nh*8 + 4];
        rv[0] += q1*r0.x; rv[1] += q1*r0.y; rv[2] += q1*r0.z; rv[3] += q1*r0.w;
        rv[4] += q1*r1.x; rv[5] += q1*r1.y; rv[6] += q1*r1.z; rv[7] += q1*r1.w;
        rw[0] += q2*r0.x; rw[1] += q2*r0.y; rw[2] += q2*r0.z; rw[3] += q2*r0.w;
        rw[4] += q2*r1.x; rw[5] += q2*r1.y; rw[6] += q2*r1.z; rw[7] += q2*r1.w;
    }
    {
        int best = 0; float bv = rv[0];
        #pragma unroll
        for (int r = 1; r < 8; r++) if (rv[r] > bv) { bv = rv[r]; best = r; }
        #pragma unroll
        for (int r = 0; r < 8; r++) { float nv = -rv[r]; if (nv > bv) { bv = nv; best = 8 + r; } }
        bkt[(bh*NHh + nh)*Tt + t0 + tl] = best;
    }
    {
        int best = 0; float bv = rw[0];
        #pragma unroll
        for (int r = 1; r < 8; r++) if (rw[r] > bv) { bv = rw[r]; best = r; }
        #pragma unroll
        for (int r = 0; r < 8; r++) { float nv = -rw[r]; if (nv > bv) { bv = nv; best = 8 + r; } }
        bkt[(bh*NHh + nh)*Tt + t0 + tl + 32] = best;
    }
}

// ---------------- stable counting sort ----------------
__global__ void sort_kernel(const int* __restrict__ bkt, int* __restrict__ st) {
    __shared__ int sb[Tt];
    __shared__ int cnt[16];
    __shared__ int off[16];
    int base = blockIdx.x*Tt;
    int tid = threadIdx.x;
    for (int i = tid; i < Tt; i += 512) sb[i] = bkt[base + i];
    __syncthreads();
    int w = tid >> 5, lane = tid & 31;
    int c = 0;
    for (int it = 0; it < 32; it++) {
        unsigned m = __ballot_sync(0xffffffffu, sb[it*32 + lane] == w);
        c += __popc(m);
    }
    if (lane == 0) cnt[w] = c;
    __syncthreads();
    if (tid == 0) {
        int s = 0;
        for (int i = 0; i < 16; i++) { off[i] = s; s += cnt[i]; }
    }
    __syncthreads();
    int p = off[w];
    for (int it = 0; it < 32; it++) {
        int t = it*32 + lane;
        int bb = sb[t];
        unsigned m = __ballot_sync(0xffffffffu, bb == w);
        if (bb == w) {
            int pos = p + __popc(m & ((1u << lane) - 1u));
            st[base + pos] = t;
        }
        p += __popc(m);
    }
}

// ---------------- chunked LSH attention (3-term bf16 k16, packed-pair tiles) ----------------
__global__ void __launch_bounds__(256,2) attn_kernel(const int* __restrict__ st,
                                                   const float* __restrict__ qk,
                                                   const float* __restrict__ vg,
                                                   float* __restrict__ slog,
                                                   float* __restrict__ bo) {
    extern __shared__ float sm[];
    unsigned* qh = (unsigned*)sm;
    unsigned* ql = qh + 64*PIT;
    unsigned* kh = ql + 64*PIT;
    unsigned* kl = kh + 64*PIT;
    float* sd   = (float*)(kl + 64*PIT);
    float* invs = sd + 64*132;
    int*   posK = (int*)(invs + 128);

    int n = blockIdx.x, bh = blockIdx.y;
    int b = bh >> 3, h = bh & 7;
    int tid = threadIdx.x;
    int nh = n >> 4;
    int segb = bh*SEG;

    const int lane = tid & 31, warp = tid >> 5;
    const int gid = lane >> 2, qid = lane & 3;

    if (tid < 128) {
        int cc = (tid < 64) ? n : ((n + NC - 1) & (NC-1));
        posK[tid] = st[segb + cc*BSz + (tid & 63)];
    }
    __syncthreads();

    for (int i = tid; i < 64*16; i += 256) {
        int r = i >> 4, c4 = (i & 15)*4;
        int wp = c4 >> 1;
        float4 a = *(const float4*)&qk[(size_t)(b*Tt + posK[r])*Dd + h*DHh + c4];
        unsigned h0, l0, h1, l1;
        split_pair(a.x, a.y, h0, l0); split_pair(a.z, a.w, h1, l1);
        qh[r*PIT + wp] = h0; qh[r*PIT + wp+1] = h1;
        ql[r*PIT + wp] = l0; ql[r*PIT + wp+1] = l1;
        float4 k2 = *(const float4*)&qk[(size_t)(b*Tt + posK[64+r])*Dd + h*DHh + c4];
        split_pair(k2.x, k2.y, h0, l0); split_pair(k2.z, k2.w, h1, l1);
        kh[r*PIT + wp] = h0; kh[r*PIT + wp+1] = h1;
        kl[r*PIT + wp] = l0; kl[r*PIT + wp+1] = l1;
    }
    __syncthreads();

    if (tid < 128) {
        const unsigned* ph = (tid < 64) ? qh : kh;
        const unsigned* pl = (tid < 64) ? ql : kl;
        int r = tid & 63;
        float s = 0.f;
        #pragma unroll 8
        for (int w = 0; w < 32; w++) {
            unsigned hw = ph[r*PIT + w], lw = pl[r*PIT + w];
            float x0 = __uint_as_float(hw << 16) + __uint_as_float(lw << 16);
            float x1 = __uint_as_float(hw & 0xffff0000u) + __uint_as_float(lw & 0xffff0000u);
            s += x0*x0 + x1*x1;
        }
        invs[tid] = 1.f/(sqrtf(s) + 1e-8f);
    }
    __syncthreads();

    {
        const int mb  = (warp & 1)*32;
        const int khh = (warp >> 1) & 1;
        const int nb  = (warp >> 2)*32;
        const unsigned* bhp = khh ? kh : qh;
        const unsigned* blp = khh ? kl : ql;
        float c[2][4][4];
        #pragma unroll
        for (int mt = 0; mt < 2; mt++)
            #pragma unroll
            for (int nt = 0; nt < 4; nt++)
                #pragma unroll
                for (int e = 0; e < 4; e++) c[mt][nt][e] = 0.f;

        #pragma unroll
        for (int kt = 0; kt < 4; kt++) {
            int kw = kt*8;
            unsigned ah[2][4], al[2][4];
            #pragma unroll
            for (int mt = 0; mt < 2; mt++) {
                int r0 = (mb + mt*16 + gid)*PIT;
                int r1 = r0 + 8*PIT;
                ah[mt][0] = qh[r0 + kw+qid];   al[mt][0] = ql[r0 + kw+qid];
                ah[mt][1] = qh[r1 + kw+qid];   al[mt][1] = ql[r1 + kw+qid];
                ah[mt][2] = qh[r0 + kw+qid+4]; al[mt][2] = ql[r0 + kw+qid+4];
                ah[mt][3] = qh[r1 + kw+qid+4]; al[mt][3] = ql[r1 + kw+qid+4];
            }
            #pragma unroll
            for (int nt = 0; nt < 4; nt++) {
                int kr = (nb + nt*8 + gid)*PIT;
                unsigned b0h = bhp[kr + kw+qid],   b0l = blp[kr + kw+qid];
                unsigned b1h = bhp[kr + kw+qid+4], b1l = blp[kr + kw+qid+4];
                #pragma unroll
                for (int mt = 0; mt < 2; mt++) {
                    mma_bf16(c[mt][nt], ah[mt][0],ah[mt][1],ah[mt][2],ah[mt][3], b0h, b1h);
                    mma_bf16(c[mt][nt], ah[mt][0],ah[mt][1],ah[mt][2],ah[mt][3], b0l, b1l);
                    mma_bf16(c[mt][nt], al[mt][0],al[mt][1],al[mt][2],al[mt][3], b0h, b1h);
                }
            }
        }
        #pragma unroll
        for (int mt = 0; mt < 2; mt++) {
            int r0 = mb + mt*16 + gid;
            int pq0 = posK[r0], pq1 = posK[r0+8];
            #pragma unroll
            for (int nt = 0; nt < 4; nt++) {
                int col = khh*64 + nb + nt*8 + qid*2;
                float is0 = invs[col]*0.125f, is1 = invs[col+1]*0.125f;
                int pk0 = posK[col], pk1 = posK[col+1];
                float s00 = c[mt][nt][0]*is0; if (pq0 == pk0) s00 = -5e4f;
                float s01 = c[mt][nt][1]*is1; if (pq0 == pk1) s01 = -5e4f;
                float s10 = c[mt][nt][2]*is0; if (pq1 == pk0) s10 = -5e4f;
                float s11 = c[mt][nt][3]*is1; if (pq1 == pk1) s11 = -5e4f;
                sd[r0*132 + col] = s00;     sd[r0*132 + col+1] = s01;
                sd[(r0+8)*132 + col] = s10; sd[(r0+8)*132 + col+1] = s11;
            }
        }
    }
    __syncthreads();

    {
        int r = tid >> 2, c4 = tid & 3;
        float vals[32];
        float mx = -1e30f;
        #pragma unroll
        for (int i = 0; i < 32; i++) { vals[i] = sd[r*132 + i*4 + c4]; mx = fmaxf(mx, vals[i]); }
        mx = fmaxf(mx, __shfl_xor_sync(0xffffffffu, mx, 1));
        mx = fmaxf(mx, __shfl_xor_sync(0xffffffffu, mx, 2));
        float se = 0.f;
        #pragma unroll
        for (int i = 0; i < 32; i++) { vals[i] = __expf(vals[i] - mx); se += vals[i]; }
        se += __shfl_xor_sync(0xffffffffu, se, 1);
        se += __shfl_xor_sync(0xffffffffu, se, 2);
        if (c4 == 0) slog[((size_t)bh*NHh + nh)*Tt + posK[r]] = mx + __logf(se);
        float inv_se = 1.f/se;
        #pragma unroll
        for (int i = 0; i < 32; i++) sd[r*132 + i*4 + c4] = vals[i]*inv_se;
    }
    __syncthreads();

    for (int i = tid; i < 1024; i += 256) {
        int half = i >> 9;
        int p  = (i >> 4) & 31;
        int d4 = (i & 15)*4;
        unsigned* vh = half ? kh : qh;
        unsigned* vl = half ? kl : ql;
        float4 a0 = *(const float4*)&vg[(size_t)(b*Tt + posK[half*64 + 2*p  ])*Dd + h*DHh + d4];
        float4 a1 = *(const float4*)&vg[(size_t)(b*Tt + posK[half*64 + 2*p+1])*Dd + h*DHh + d4];
        unsigned hw, lw;
        split_pair(a0.x, a1.x, hw, lw); vh[(d4+0)*PIT + p] = hw; vl[(d4+0)*PIT + p] = lw;
        split_pair(a0.y, a1.y, hw, lw); vh[(d4+1)*PIT + p] = hw; vl[(d4+1)*PIT + p] = lw;
        split_pair(a0.z, a1.z, hw, lw); vh[(d4+2)*PIT + p] = hw; vl[(d4+2)*PIT + p] = lw;
        split_pair(a0.w, a1.w, hw, lw); vh[(d4+3)*PIT + p] = hw; vl[(d4+3)*PIT + p] = lw;
    }
    __syncthreads();

    {
        const int mb = (warp & 1)*32;
        const int db = ((warp >> 1) & 3)*16;
        float c[2][2][4];
        #pragma unroll
        for (int mt = 0; mt < 2; mt++)
            #pragma unroll
            for (int nt = 0; nt < 2; nt++)
                #pragma unroll
                for (int e = 0; e < 4; e++) c[mt][nt][e] = 0.f;

        #pragma unroll
        for (int kt = 0; kt < 8; kt++) {
            int k0 = kt*16;
            const unsigned* vh = (kt < 4) ? qh : kh;
            const unsigned* vl = (kt < 4) ? ql : kl;
            int kw = (kt & 3)*8;
            unsigned ah[2][4], al[2][4];
            #pragma unroll
            for (int mt = 0; mt < 2; mt++) {
                int r0 = (mb + mt*16 + gid)*132;
                int r1 = r0 + 8*132;
                split_pair(sd[r0 + k0+2*qid],   sd[r0 + k0+2*qid+1],   ah[mt][0], al[mt][0]);
                split_pair(sd[r1 + k0+2*qid],   sd[r1 + k0+2*qid+1],   ah[mt][1], al[mt][1]);
                split_pair(sd[r0 + k0+2*qid+8], sd[r0 + k0+2*qid+9],   ah[mt][2], al[mt][2]);
                split_pair(sd[r1 + k0+2*qid+8], sd[r1 + k0+2*qid+9],   ah[mt][3], al[mt][3]);
            }
            #pragma unroll
            for (int nt = 0; nt < 2; nt++) {
                int d = db + nt*8 + gid;
                unsigned b0h = vh[d*PIT + kw + qid],   b0l = vl[d*PIT + kw + qid];
                unsigned b1h = vh[d*PIT + kw + qid+4], b1l = vl[d*PIT + kw + qid+4];
                #pragma unroll
                for (int mt = 0; mt < 2; mt++) {
                    mma_bf16(c[mt][nt], ah[mt][0],ah[mt][1],ah[mt][2],ah[mt][3], b0h, b1h);
                    mma_bf16(c[mt][nt], ah[mt][0],ah[mt][1],ah[mt][2],ah[mt][3], b0l, b1l);
                    mma_bf16(c[mt][nt], al[mt][0],al[mt][1],al[mt][2],al[mt][3], b0h, b1h);
                }
            }
        }
        size_t base0 = ((size_t)bh*NHh + nh)*Tt;
        #pragma unroll
        for (int mt = 0; mt < 2; mt++) {
            int r0 = mb + mt*16 + gid;
            float* bo0 = &bo[(base0 + posK[r0])*DHh];
            float* bo1 = &bo[(base0 + posK[r0+8])*DHh];
            #pragma unroll
            for (int nt = 0; nt < 2; nt++) {
                int col = db + nt*8 + qid*2;
                bo0[col] = c[mt][nt][0]; bo0[col+1] = c[mt][nt][1];
                bo1[col] = c[mt][nt][2]; bo1[col+1] = c[mt][nt][3];
            }
        }
    }
}

// ---------------- combine: writes packed hi/lo ao ----------------
__global__ void combine_kernel(const float* __restrict__ slog,
                               const float* __restrict__ bo,
                               unsigned* __restrict__ aoh, unsigned* __restrict__ aol) {
    int idx = blockIdx.x*256 + threadIdx.x;
    if (idx >= BHn*Tt*16) return;
    int d4 = (idx & 15)*4;
    int t  = (idx >> 4) & (Tt-1);
    int bh = idx >> 14;
    float lg[NHh];
    float mx = -1e30f;
    #pragma unroll
    for (int i = 0; i < NHh; i++) {
        lg[i] = slog[((size_t)bh*NHh + i)*Tt + t];
        mx = fmaxf(mx, lg[i]);
    }
    float se = 0.f;
    #pragma unroll
    for (int i = 0; i < NHh; i++) { lg[i] = __expf(lg[i] - mx); se += lg[i]; }
    float inv = 1.f/se;
    float4 out = make_float4(0.f, 0.f, 0.f, 0.f);
    #pragma unroll
    for (int i = 0; i < NHh; i++) {
        float w = lg[i]*inv;
        float4 bv = *(const float4*)&bo[(((size_t)bh*NHh + i)*Tt + t)*DHh + d4];
        out.x += w*bv.x; out.y += w*bv.y; out.z += w*bv.z; out.w += w*bv.w;
    }
    int b = bh >> 3, h = bh & 7;
    unsigned h0, l0, h1, l1;
    split_pair(out.x, out.y, h0, l0);
    split_pair(out.z, out.w, h1, l1);
    size_t base = (size_t)(b*Tt + t)*256 + ((h*DHh + d4) >> 1);
    aoh[base] = h0; aoh[base+1] = h1;
    aol[base] = l0; aol[base+1] = l1;
}

// ---------------- pooling (reads split xn) + fc ----------------
__global__ void pool_kernel(const unsigned* __restrict__ xh, const unsigned* __restrict__ xl,
                            float* __restrict__ pool) {
    int b = blockIdx.x, d = threadIdx.x;
    int w = d >> 1, part = d & 1;
    float s = 0.f;
    for (int t = 0; t < Tt; t++) {
        unsigned hw = xh[(size_t)(b*Tt + t)*256 + w];
        unsigned lw = xl[(size_t)(b*Tt + t)*256 + w];
        float xv;
        if (part) xv = __uint_as_float(hw & 0xffff0000u) + __uint_as_float(lw & 0xffff0000u);
        else      xv = __uint_as_float(hw << 16) + __uint_as_float(lw << 16);
        s += xv;
    }
    pool[b*Dd + d] = s * (1.f/(float)Tt);
}

__global__ void fc_kernel(const float* __restrict__ pool,
                          const float* __restrict__ Wfc, float* __restrict__ out) {
    int b = blockIdx.x, n = threadIdx.x;
    float s = 0.f;
    for (int kk = 0; kk < Dd; kk++) s += pool[b*Dd + kk]*Wfc[kk*Dd + n];
    out[b*Dd + n] = s;
}

// ---------------- orchestration ----------------
extern "C" void kernel_launch(void* const* d_in, const int* in_sizes, int n_in,
                              void* d_out, int out_size) {
    const int*   ids = (const int*)  d_in[0];
    const float* tok = (const float*)d_in[1];
    const float* pos = (const float*)d_in[2];
    const float* lag = (const float*)d_in[3];
    const float* lab = (const float*)d_in[4];
    const float* Wqk = (const float*)d_in[5];
    const float* Wv  = (const float*)d_in[6];
    const float* Wo  = (const float*)d_in[7];
    const float* lfg = (const float*)d_in[8];
    const float* lfb = (const float*)d_in[9];
    const float* W1  = (const float*)d_in[10];
    const float* b1  = (const float*)d_in[11];
    const float* W2  = (const float*)d_in[12];
    const float* b2  = (const float*)d_in[13];
    const float* lng = (const float*)d_in[14];
    const float* lnb = (const float*)d_in[15];
    const float* Wfc = (const float*)d_in[16];
    const float* rot = (const float*)d_in[17];
    float* out = (float*)d_out;

    float *x1, *x2, *qk, *v, *bo, *slog, *pool;
    int *st, *bkt;
    unsigned *xnh, *xnl, *ffhh, *ffhl, *aoh, *aol;
    unsigned *wqkh, *wqkl, *wvh, *wvl, *woh, *wol, *w1h, *w1l, *w2h, *w2l;
    cudaGetSymbolAddress((void**)&x1,   g_x1);
    cudaGetSymbolAddress((void**)&x2,   g_x2);
    cudaGetSymbolAddress((void**)&qk,   g_qk);
    cudaGetSymbolAddress((void**)&v,    g_v);
    cudaGetSymbolAddress((void**)&bo,   g_bo);
    cudaGetSymbolAddress((void**)&slog, g_slog);
    cudaGetSymbolAddress((void**)&pool, g_pool);
    cudaGetSymbolAddress((void**)&st,   g_st);
    cudaGetSymbolAddress((void**)&bkt,  g_bkt);
    cudaGetSymbolAddress((void**)&xnh,  g_xnh);
    cudaGetSymbolAddress((void**)&xnl,  g_xnl);
    cudaGetSymbolAddress((void**)&ffhh, g_ffhh);
    cudaGetSymbolAddress((void**)&ffhl, g_ffhl);
    cudaGetSymbolAddress((void**)&aoh,  g_aoh);
    cudaGetSymbolAddress((void**)&aol,  g_aol);
    cudaGetSymbolAddress((void**)&wqkh, g_WqkH);
    cudaGetSymbolAddress((void**)&wqkl, g_WqkL);
    cudaGetSymbolAddress((void**)&wvh,  g_WvH);
    cudaGetSymbolAddress((void**)&wvl,  g_WvL);
    cudaGetSymbolAddress((void**)&woh,  g_WoH);
    cudaGetSymbolAddress((void**)&wol,  g_WoL);
    cudaGetSymbolAddress((void**)&w1h,  g_W1H);
    cudaGetSymbolAddress((void**)&w1l,  g_W1L);
    cudaGetSymbolAddress((void**)&w2h,  g_W2H);
    cudaGetSymbolAddress((void**)&w2l,  g_W2L);

    const int ATTN_SMEM = 4*64*PIT*4 + 64*132*4 + 128*4 + 128*4;   // 71680
    cudaFuncSetAttribute(attn_kernel, cudaFuncAttributeMaxDynamicSharedMemorySize, ATTN_SMEM);

    const int M = Bb*Tt;

    // pre-split all weights into bf16 hi/lo pair-packed buffers
    convw_kernel<<<(DEPTHL*256*512 + 255)/256, 256>>>(Wqk, wqkh, wqkl, DEPTHL*256, 512);
    convw_kernel<<<(DEPTHL*256*512 + 255)/256, 256>>>(Wv,  wvh,  wvl,  DEPTHL*256, 512);
    convw_kernel<<<(DEPTHL*256*512 + 255)/256, 256>>>(Wo,  woh,  wol,  DEPTHL*256, 512);
    convw_kernel<<<(DEPTHL*256*2048 + 255)/256, 256>>>(W1, w1h, w1l, DEPTHL*256, 2048);
    convw_kernel<<<(DEPTHL*1024*512 + 255)/256, 256>>>(W2, w2h, w2l, DEPTHL*1024, 512);

    embed_kernel<<<(Bb*Tt*Dd + 255)/256, 256>>>(ids, tok, pos, x1, x2);

    for (int l = 0; l < DEPTHL; l++) {
        const unsigned* wqkh_l = wqkh + (size_t)l*256*512;
        const unsigned* wqkl_l = wqkl + (size_t)l*256*512;
        const unsigned* wvh_l  = wvh  + (size_t)l*256*512;
        const unsigned* wvl_l  = wvl  + (size_t)l*256*512;
        const unsigned* woh_l  = woh  + (size_t)l*256*512;
        const unsigned* wol_l  = wol  + (size_t)l*256*512;
        const unsigned* w1h_l  = w1h  + (size_t)l*256*2048;
        const unsigned* w1l_l  = w1l  + (size_t)l*256*2048;
        const unsigned* w2h_l  = w2h  + (size_t)l*1024*512;
        const unsigned* w2l_l  = w2l  + (size_t)l*1024*512;
        const float* b1_l  = b1  + (size_t)l*FFf;
        const float* b2_l  = b2  + (size_t)l*Dd;
        const float* rot_l = rot + (size_t)l*DHh*64;

        // attention block: x1 += attn(LN(x2)) @ Wo
        ln_kernel<<<M, 256>>>(x2, nullptr, xnh, xnl, lag + l*Dd, lab + l*Dd);
        gemm_kernel<0><<<dim3(1024/128, M/128), 256>>>(xnh, xnl, wqkh_l, wqkl_l,
            nullptr, qk, nullptr, nullptr, M, Dd, wvh_l, wvl_l, v, Dd, Dd);
        hash_kernel<<<BHn*16, 256>>>(rot_l, qk, bkt);
        sort_kernel<<<BHn*NHh, 512>>>(bkt, st);
        attn_kernel<<<dim3(NC, BHn), 256, ATTN_SMEM>>>(st, qk, v, slog, bo);
        combine_kernel<<<(BHn*Tt*16)/256, 256>>>(slog, bo, aoh, aol);
        gemm_kernel<3><<<dim3(Dd/128, M/128), 256>>>(aoh, aol, woh_l, wol_l,
            nullptr, x1, nullptr, nullptr, M, Dd, nullptr, nullptr, nullptr, 0, Dd);

        // feed-forward block: x2 += gelu(LN(x1)@W1 + b1) @ W2 + b2
        ln_kernel<<<M, 256>>>(x1, nullptr, xnh, xnl, lfg + l*Dd, lfb + l*Dd);
        gemm_kernel<1><<<dim3(FFf/128, M/128), 256>>>(xnh, xnl, w1h_l, w1l_l,
            b1_l, nullptr, ffhh, ffhl, M, Dd, nullptr, nullptr, nullptr, 0, FFf);
        gemm_kernel<4><<<dim3(Dd/128, M/128), 256>>>(ffhh, ffhl, w2h_l, w2l_l,
            b2_l, x2, nullptr, nullptr, M, FFf, nullptr, nullptr, nullptr, 0, Dd);
    }

    // final: 0.5*(x1+x2) -> LN -> mean over T -> @ Wfc
    ln_kernel<<<M, 256>>>(x1, x2, xnh, xnl, lng, lnb);
    pool_kernel<<<Bb, Dd>>>(xnh, xnl, pool);
    fc_kernel<<<Bb, Dd>>>(pool, Wfc, out);
}